// round 12
// baseline (speedup 1.0000x reference)
#include <cuda_runtime.h>
#include <cuda_fp16.h>
#include <math.h>
#include <stdint.h>

#define N_NODES 50000
#define IN_DIM 128
#define OUT_DIM 128
#define HEADS 4
#define HEAD_DIM 32
#define N_EDGES 800000
#define LN_EPS 1e-5f
#define NEG_SLOPE 0.2f

// ---------------- scratch (device globals; no allocation allowed) ----------
__device__ __half g_hh[(size_t)N_NODES * OUT_DIM];    // x @ W in fp16
__device__ float g_sum[(size_t)N_NODES * OUT_DIM];    // neighbor-weighted sums
__device__ float g_asrc[N_NODES * HEADS];
__device__ float g_adst[N_NODES * HEADS];
__device__ float g_den[N_NODES * HEADS];
__device__ int   g_deg[N_NODES];
__device__ int   g_start[N_NODES];
__device__ int   g_cursor[N_NODES];
__device__ int   g_csr[N_EDGES];                      // src ids grouped by dst
__device__ int   g_is64;

union H2x2 { uint2 u; __half2 h[2]; };

// ---------------- dtype detection: int64 vs int32 edge_index ---------------
__global__ void detect_kernel(const int* __restrict__ ei) {
    int t = threadIdx.x;
    long long w = 1 + 2LL * (long long)t * 1560LL;    // odd word indices < 1.6M
    int nz = (ei[w] != 0);
    int any = __syncthreads_or(nz);
    if (t == 0) g_is64 = any ? 0 : 1;
}

__global__ void zero_deg_kernel() {
    int i = blockIdx.x * blockDim.x + threadIdx.x;
    if (i < N_NODES) g_deg[i] = 0;
}

// ---------------- GEMM: h = x @ W (fp32 compute, fp16 store) ---------------
__global__ __launch_bounds__(256) void gemm_kernel(const float* __restrict__ x,
                                                   const float* __restrict__ W,
                                                   const float* __restrict__ att_src,
                                                   const float* __restrict__ att_dst) {
    extern __shared__ float sm[];
    float* Xs = sm;                         // [64][128] = 32KB
    float* Wb[2] = { sm + 8192, sm + 8192 + 4096 };   // 2 x [32][128] = 32KB
    int t = threadIdx.x;
    int row0 = blockIdx.x * 64;

    const float4* x4 = reinterpret_cast<const float4*>(x);
    const float4* W4 = reinterpret_cast<const float4*>(W);

    #pragma unroll
    for (int i = 0; i < 8; i++) {
        int idx = t + i * 256;
        int r = idx >> 5, c = idx & 31;
        int row = row0 + r;
        const float4* g = x4 + (size_t)min(row, N_NODES - 1) * 32 + c;
        uint32_t sa = (uint32_t)__cvta_generic_to_shared(Xs + idx * 4);
        int sz = (row < N_NODES) ? 16 : 0;
        asm volatile("cp.async.cg.shared.global [%0], [%1], 16, %2;"
                     :: "r"(sa), "l"(g), "r"(sz));
    }
    #pragma unroll
    for (int i = 0; i < 4; i++) {
        int idx = t + i * 256;
        uint32_t sa = (uint32_t)__cvta_generic_to_shared(Wb[0] + idx * 4);
        asm volatile("cp.async.cg.shared.global [%0], [%1], 16;"
                     :: "r"(sa), "l"(W4 + idx));
    }
    asm volatile("cp.async.commit_group;");
    #pragma unroll
    for (int i = 0; i < 4; i++) {
        int idx = t + i * 256;
        uint32_t sa = (uint32_t)__cvta_generic_to_shared(Wb[1] + idx * 4);
        asm volatile("cp.async.cg.shared.global [%0], [%1], 16;"
                     :: "r"(sa), "l"(W4 + 1024 + idx));
    }
    asm volatile("cp.async.commit_group;");

    int tr = (t >> 4) * 4;
    int tc = (t & 15) * 4;                  // group0: tc..tc+3, group1: +64
    float acc0[4][4] = {};
    float acc1[4][4] = {};

    #pragma unroll
    for (int c = 0; c < 4; c++) {
        if (c == 3) asm volatile("cp.async.wait_group 0;");
        else        asm volatile("cp.async.wait_group 1;");
        __syncthreads();

        const float* Wc = Wb[c & 1];
        #pragma unroll 8
        for (int kk = 0; kk < 32; kk++) {
            int k = c * 32 + kk;
            float4 w0 = *reinterpret_cast<const float4*>(&Wc[kk * 128 + tc]);
            float4 w1 = *reinterpret_cast<const float4*>(&Wc[kk * 128 + tc + 64]);
            #pragma unroll
            for (int i = 0; i < 4; i++) {
                float xv = Xs[(tr + i) * 128 + k];
                acc0[i][0] += xv * w0.x; acc0[i][1] += xv * w0.y;
                acc0[i][2] += xv * w0.z; acc0[i][3] += xv * w0.w;
                acc1[i][0] += xv * w1.x; acc1[i][1] += xv * w1.y;
                acc1[i][2] += xv * w1.z; acc1[i][3] += xv * w1.w;
            }
        }

        if (c < 2) {
            __syncthreads();
            #pragma unroll
            for (int i = 0; i < 4; i++) {
                int idx = t + i * 256;
                uint32_t sa = (uint32_t)__cvta_generic_to_shared(Wb[c & 1] + idx * 4);
                asm volatile("cp.async.cg.shared.global [%0], [%1], 16;"
                             :: "r"(sa), "l"(W4 + (c + 2) * 1024 + idx));
            }
            asm volatile("cp.async.commit_group;");
        }
    }

    #pragma unroll
    for (int i = 0; i < 4; i++) {
        int row = row0 + tr + i;
        if (row < N_NODES) {
            H2x2 v0, v1;
            v0.h[0] = __floats2half2_rn(acc0[i][0], acc0[i][1]);
            v0.h[1] = __floats2half2_rn(acc0[i][2], acc0[i][3]);
            v1.h[0] = __floats2half2_rn(acc1[i][0], acc1[i][1]);
            v1.h[1] = __floats2half2_rn(acc1[i][2], acc1[i][3]);
            *reinterpret_cast<uint2*>(&g_hh[(size_t)row * 128 + tc])      = v0.u;
            *reinterpret_cast<uint2*>(&g_hh[(size_t)row * 128 + tc + 64]) = v1.u;
        }
    }

    // ---- fused attention logits (fp32 accs) ----
    float as0[4], ad0[4], as1[4], ad1[4];
    #pragma unroll
    for (int j = 0; j < 4; j++) {
        as0[j] = __ldg(att_src + tc + j);
        ad0[j] = __ldg(att_dst + tc + j);
        as1[j] = __ldg(att_src + tc + 64 + j);
        ad1[j] = __ldg(att_dst + tc + 64 + j);
    }
    int h0 = tc >> 5;                       // 0 or 1; group1 head = h0+2
    #pragma unroll
    for (int i = 0; i < 4; i++) {
        float ps0 = 0.f, pd0 = 0.f, ps1 = 0.f, pd1 = 0.f;
        #pragma unroll
        for (int j = 0; j < 4; j++) {
            ps0 += acc0[i][j] * as0[j];
            pd0 += acc0[i][j] * ad0[j];
            ps1 += acc1[i][j] * as1[j];
            pd1 += acc1[i][j] * ad1[j];
        }
        #pragma unroll
        for (int o = 1; o < 8; o <<= 1) {
            ps0 += __shfl_xor_sync(0xffffffffu, ps0, o);
            pd0 += __shfl_xor_sync(0xffffffffu, pd0, o);
            ps1 += __shfl_xor_sync(0xffffffffu, ps1, o);
            pd1 += __shfl_xor_sync(0xffffffffu, pd1, o);
        }
        int row = row0 + tr + i;
        if ((t & 7) == 0 && row < N_NODES) {
            g_asrc[row * 4 + h0]     = ps0;
            g_asrc[row * 4 + h0 + 2] = ps1;
            g_adst[row * 4 + h0]     = pd0;
            g_adst[row * 4 + h0 + 2] = pd1;
        }
    }
}

// ---------------- CSR build: histogram -> scan -> scatter ------------------
__global__ __launch_bounds__(256) void hist_kernel(const int* __restrict__ ei) {
    int e = blockIdx.x * blockDim.x + threadIdx.x;
    if (e >= N_EDGES) return;
    int d = g_is64 ? ei[2 * (N_EDGES + e)] : ei[N_EDGES + e];
    atomicAdd(&g_deg[d], 1);
}

__global__ __launch_bounds__(1024) void scan_kernel() {
    __shared__ int smem[1024];
    int t = threadIdx.x;
    int lo = t * 49;
    int hi = min(lo + 49, N_NODES);
    int s = 0;
    for (int i = lo; i < hi; i++) s += g_deg[i];
    smem[t] = s;
    __syncthreads();
    for (int off = 1; off < 1024; off <<= 1) {
        int v = (t >= off) ? smem[t - off] : 0;
        __syncthreads();
        smem[t] += v;
        __syncthreads();
    }
    int run = (t == 0) ? 0 : smem[t - 1];
    for (int i = lo; i < hi; i++) {
        g_start[i]  = run;
        g_cursor[i] = run;
        run += g_deg[i];
    }
}

__global__ __launch_bounds__(256) void scatter_kernel(const int* __restrict__ ei) {
    int e = blockIdx.x * blockDim.x + threadIdx.x;
    if (e >= N_EDGES) return;
    int s, d;
    if (g_is64) { s = ei[2 * e]; d = ei[2 * (N_EDGES + e)]; }
    else        { s = ei[e];     d = ei[N_EDGES + e]; }
    int pos = atomicAdd(&g_cursor[d], 1);
    g_csr[pos] = s;
}

// ---------------- aggregation A: lean gather (warp per dst node) -----------
// No epilogue fused -> low register count, high occupancy for latency hiding.
// Writes raw neighbor sums (fp32, coalesced) and per-head denominators.
__global__ __launch_bounds__(256, 5) void aggA_kernel() {
    __shared__ float s_ex[8][128];          // [warp][edge*4+head]
    int n = (int)(((size_t)blockIdx.x * blockDim.x + threadIdx.x) >> 5);
    int lane = threadIdx.x & 31;
    int w = (threadIdx.x >> 5);
    if (n >= N_NODES) return;
    int head = lane >> 3;

    float4 ad4 = *reinterpret_cast<const float4*>(g_adst + (size_t)n * 4);
    int deg = g_deg[n];
    int st  = g_start[n];

    float4 acc = make_float4(0.f, 0.f, 0.f, 0.f);
    float den = 0.f;

    for (int base = 0; base < deg; base += 32) {
        int rem = deg - base;
        int idx = base + ((lane < rem) ? lane : (rem - 1));   // alias tail
        bool valid = lane < rem;
        int s_l = __ldg(&g_csr[st + idx]);

        // phase A: 4 head-exps for my edge
        float4 as4 = __ldg(reinterpret_cast<const float4*>(g_asrc + (size_t)s_l * 4));
        float e0 = as4.x + ad4.x, e1 = as4.y + ad4.y;
        float e2 = as4.z + ad4.z, e3 = as4.w + ad4.w;
        e0 = e0 > 0.f ? e0 : NEG_SLOPE * e0;
        e1 = e1 > 0.f ? e1 : NEG_SLOPE * e1;
        e2 = e2 > 0.f ? e2 : NEG_SLOPE * e2;
        e3 = e3 > 0.f ? e3 : NEG_SLOPE * e3;
        float4 ex4;
        ex4.x = valid ? __expf(e0) : 0.f;
        ex4.y = valid ? __expf(e1) : 0.f;
        ex4.z = valid ? __expf(e2) : 0.f;
        ex4.w = valid ? __expf(e3) : 0.f;
        *reinterpret_cast<float4*>(&s_ex[w][lane * 4]) = ex4;
        __syncwarp();

        // phase B: pipelined fp16 gather
        int cnt8 = min(32, (rem + 7) & ~7);
        #pragma unroll 8
        for (int i = 0; i < cnt8; i++) {
            int s = __shfl_sync(0xffffffffu, s_l, i);
            float ex = s_ex[w][i * 4 + head];
            H2x2 v;
            v.u = __ldg(reinterpret_cast<const uint2*>(
                g_hh + (size_t)s * 128 + lane * 4));
            float2 f0 = __half22float2(v.h[0]);
            float2 f1 = __half22float2(v.h[1]);
            acc.x += f0.x * ex; acc.y += f0.y * ex;
            acc.z += f1.x * ex; acc.w += f1.y * ex;
            den += ex;
        }
        __syncwarp();
    }

    *reinterpret_cast<float4*>(&g_sum[(size_t)n * 128 + lane * 4]) = acc;
    if ((lane & 7) == 0) g_den[n * 4 + head] = den;
}

// ---------------- aggregation B: self-loop + normalize + LN + GELU ---------
__global__ __launch_bounds__(256) void aggB_kernel(const float* __restrict__ x,
                                                   const float* __restrict__ bias,
                                                   const float* __restrict__ gamma,
                                                   const float* __restrict__ beta,
                                                   float* __restrict__ out) {
    int n = (int)(((size_t)blockIdx.x * blockDim.x + threadIdx.x) >> 5);
    int lane = threadIdx.x & 31;
    if (n >= N_NODES) return;
    int head = lane >> 3;

    float ash = g_asrc[n * 4 + head];
    float adh = g_adst[n * 4 + head];
    float e = ash + adh;
    e = e > 0.f ? e : NEG_SLOPE * e;
    float ex = __expf(e);
    float den = g_den[n * 4 + head] + ex;
    float inv = 1.f / den;

    float4 acc = *reinterpret_cast<const float4*>(g_sum + (size_t)n * 128 + lane * 4);
    H2x2 v;
    v.u = *reinterpret_cast<const uint2*>(g_hh + (size_t)n * 128 + lane * 4);
    float2 f0 = __half22float2(v.h[0]);
    float2 f1 = __half22float2(v.h[1]);

    float4 b4 = __ldg(reinterpret_cast<const float4*>(bias + lane * 4));
    float v0 = (acc.x + f0.x * ex) * inv + b4.x;
    float v1 = (acc.y + f0.y * ex) * inv + b4.y;
    float v2 = (acc.z + f1.x * ex) * inv + b4.z;
    float v3 = (acc.w + f1.y * ex) * inv + b4.w;

    // LayerNorm over 128 channels (warp allreduce)
    float s = v0 + v1 + v2 + v3;
    #pragma unroll
    for (int o = 16; o > 0; o >>= 1) s += __shfl_xor_sync(0xffffffffu, s, o);
    float mu = s * (1.f / 128.f);
    float d0 = v0 - mu, d1 = v1 - mu, d2 = v2 - mu, d3 = v3 - mu;
    float q = d0 * d0 + d1 * d1 + d2 * d2 + d3 * d3;
    #pragma unroll
    for (int o = 16; o > 0; o >>= 1) q += __shfl_xor_sync(0xffffffffu, q, o);
    float rstd = rsqrtf(q * (1.f / 128.f) + LN_EPS);

    float4 gm = __ldg(reinterpret_cast<const float4*>(gamma + lane * 4));
    float4 bt = __ldg(reinterpret_cast<const float4*>(beta + lane * 4));
    float4 xv = *reinterpret_cast<const float4*>(x + (size_t)n * 128 + lane * 4);

    float h0 = d0 * rstd * gm.x + bt.x + xv.x;
    float h1 = d1 * rstd * gm.y + bt.y + xv.y;
    float h2 = d2 * rstd * gm.z + bt.z + xv.z;
    float h3 = d3 * rstd * gm.w + bt.w + xv.w;

    const float kk = 0.70710678118654752f;
    float4 r;
    r.x = 0.5f * h0 * (1.f + erff(h0 * kk));
    r.y = 0.5f * h1 * (1.f + erff(h1 * kk));
    r.z = 0.5f * h2 * (1.f + erff(h2 * kk));
    r.w = 0.5f * h3 * (1.f + erff(h3 * kk));
    *reinterpret_cast<float4*>(out + (size_t)n * 128 + lane * 4) = r;
}

// ---------------- launch ----------------------------------------------------
extern "C" void kernel_launch(void* const* d_in, const int* in_sizes, int n_in,
                              void* d_out, int out_size) {
    const float* x       = (const float*)d_in[0];
    const int*   ei      = (const int*)d_in[1];   // int32 or int64 (detected)
    const float* W       = (const float*)d_in[2];
    const float* att_src = (const float*)d_in[3];
    const float* att_dst = (const float*)d_in[4];
    const float* bias    = (const float*)d_in[5];
    const float* gamma   = (const float*)d_in[6];
    const float* beta    = (const float*)d_in[7];
    float* out = (float*)d_out;

    cudaFuncSetAttribute(gemm_kernel, cudaFuncAttributeMaxDynamicSharedMemorySize,
                         65536);

    detect_kernel<<<1, 512>>>(ei);
    zero_deg_kernel<<<(N_NODES + 255) / 256, 256>>>();
    hist_kernel<<<(N_EDGES + 255) / 256, 256>>>(ei);
    gemm_kernel<<<(N_NODES + 63) / 64, 256, 65536>>>(x, W, att_src, att_dst);
    scan_kernel<<<1, 1024>>>();
    scatter_kernel<<<(N_EDGES + 255) / 256, 256>>>(ei);
    aggA_kernel<<<(N_NODES + 7) / 8, 256>>>();
    aggB_kernel<<<(N_NODES + 7) / 8, 256>>>(x, bias, gamma, beta, out);
}

// round 13
// speedup vs baseline: 1.2375x; 1.2375x over previous
#include <cuda_runtime.h>
#include <cuda_fp16.h>
#include <math.h>
#include <stdint.h>

#define N_NODES 50000
#define IN_DIM 128
#define OUT_DIM 128
#define HEADS 4
#define HEAD_DIM 32
#define N_EDGES 800000
#define LN_EPS 1e-5f
#define NEG_SLOPE 0.2f

// ---------------- scratch (device globals; no allocation allowed) ----------
__device__ __half g_hh[(size_t)N_NODES * OUT_DIM];    // x @ W in fp16
__device__ float g_out[(size_t)N_NODES * OUT_DIM];    // unnormalized message sums
__device__ float g_asrc[N_NODES * HEADS];
__device__ float g_adst[N_NODES * HEADS];
__device__ float g_den[N_NODES * HEADS];
__device__ int   g_is64;

union H2x2 { uint2 u; __half2 h[2]; };

// ---------------- dtype detection: int64 vs int32 edge_index ---------------
__global__ void detect_kernel(const int* __restrict__ ei) {
    int t = threadIdx.x;
    long long w = 1 + 2LL * (long long)t * 1560LL;    // odd word indices < 1.6M
    int nz = (ei[w] != 0);
    int any = __syncthreads_or(nz);
    if (t == 0) g_is64 = any ? 0 : 1;
}

// ---------------- zero accumulators ----------------------------------------
__global__ void zero_kernel() {
    size_t tid    = (size_t)blockIdx.x * blockDim.x + threadIdx.x;
    size_t stride = (size_t)gridDim.x * blockDim.x;
    float4 z = make_float4(0.f, 0.f, 0.f, 0.f);
    float4* o4 = reinterpret_cast<float4*>(g_out);
    for (size_t i = tid; i < (size_t)N_NODES * OUT_DIM / 4; i += stride) o4[i] = z;
    float4* d4 = reinterpret_cast<float4*>(g_den);
    for (size_t i = tid; i < (size_t)N_NODES * HEADS / 4; i += stride) d4[i] = z;
}

// ---------------- GEMM: h = x @ W (fp32 compute, fp16 store) ---------------
// 64 rows x 128 cols per block; 256 threads, each 4 rows x (4+4) cols.
// W double-buffered via cp.async; fused attention logits from fp32 accs.
__global__ __launch_bounds__(256) void gemm_kernel(const float* __restrict__ x,
                                                   const float* __restrict__ W,
                                                   const float* __restrict__ att_src,
                                                   const float* __restrict__ att_dst) {
    extern __shared__ float sm[];
    float* Xs = sm;                         // [64][128] = 32KB
    float* Wb[2] = { sm + 8192, sm + 8192 + 4096 };   // 2 x [32][128] = 32KB
    int t = threadIdx.x;
    int row0 = blockIdx.x * 64;

    const float4* x4 = reinterpret_cast<const float4*>(x);
    const float4* W4 = reinterpret_cast<const float4*>(W);

    #pragma unroll
    for (int i = 0; i < 8; i++) {
        int idx = t + i * 256;
        int r = idx >> 5, c = idx & 31;
        int row = row0 + r;
        const float4* g = x4 + (size_t)min(row, N_NODES - 1) * 32 + c;
        uint32_t sa = (uint32_t)__cvta_generic_to_shared(Xs + idx * 4);
        int sz = (row < N_NODES) ? 16 : 0;
        asm volatile("cp.async.cg.shared.global [%0], [%1], 16, %2;"
                     :: "r"(sa), "l"(g), "r"(sz));
    }
    #pragma unroll
    for (int i = 0; i < 4; i++) {
        int idx = t + i * 256;
        uint32_t sa = (uint32_t)__cvta_generic_to_shared(Wb[0] + idx * 4);
        asm volatile("cp.async.cg.shared.global [%0], [%1], 16;"
                     :: "r"(sa), "l"(W4 + idx));
    }
    asm volatile("cp.async.commit_group;");
    #pragma unroll
    for (int i = 0; i < 4; i++) {
        int idx = t + i * 256;
        uint32_t sa = (uint32_t)__cvta_generic_to_shared(Wb[1] + idx * 4);
        asm volatile("cp.async.cg.shared.global [%0], [%1], 16;"
                     :: "r"(sa), "l"(W4 + 1024 + idx));
    }
    asm volatile("cp.async.commit_group;");

    int tr = (t >> 4) * 4;
    int tc = (t & 15) * 4;                  // group0: tc..tc+3, group1: +64
    float acc0[4][4] = {};
    float acc1[4][4] = {};

    #pragma unroll
    for (int c = 0; c < 4; c++) {
        if (c == 3) asm volatile("cp.async.wait_group 0;");
        else        asm volatile("cp.async.wait_group 1;");
        __syncthreads();

        const float* Wc = Wb[c & 1];
        #pragma unroll 8
        for (int kk = 0; kk < 32; kk++) {
            int k = c * 32 + kk;
            float4 w0 = *reinterpret_cast<const float4*>(&Wc[kk * 128 + tc]);
            float4 w1 = *reinterpret_cast<const float4*>(&Wc[kk * 128 + tc + 64]);
            #pragma unroll
            for (int i = 0; i < 4; i++) {
                float xv = Xs[(tr + i) * 128 + k];
                acc0[i][0] += xv * w0.x; acc0[i][1] += xv * w0.y;
                acc0[i][2] += xv * w0.z; acc0[i][3] += xv * w0.w;
                acc1[i][0] += xv * w1.x; acc1[i][1] += xv * w1.y;
                acc1[i][2] += xv * w1.z; acc1[i][3] += xv * w1.w;
            }
        }

        if (c < 2) {
            __syncthreads();
            #pragma unroll
            for (int i = 0; i < 4; i++) {
                int idx = t + i * 256;
                uint32_t sa = (uint32_t)__cvta_generic_to_shared(Wb[c & 1] + idx * 4);
                asm volatile("cp.async.cg.shared.global [%0], [%1], 16;"
                             :: "r"(sa), "l"(W4 + (c + 2) * 1024 + idx));
            }
            asm volatile("cp.async.commit_group;");
        }
    }

    #pragma unroll
    for (int i = 0; i < 4; i++) {
        int row = row0 + tr + i;
        if (row < N_NODES) {
            H2x2 v0, v1;
            v0.h[0] = __floats2half2_rn(acc0[i][0], acc0[i][1]);
            v0.h[1] = __floats2half2_rn(acc0[i][2], acc0[i][3]);
            v1.h[0] = __floats2half2_rn(acc1[i][0], acc1[i][1]);
            v1.h[1] = __floats2half2_rn(acc1[i][2], acc1[i][3]);
            *reinterpret_cast<uint2*>(&g_hh[(size_t)row * 128 + tc])      = v0.u;
            *reinterpret_cast<uint2*>(&g_hh[(size_t)row * 128 + tc + 64]) = v1.u;
        }
    }

    // ---- fused attention logits (fp32 accs) ----
    float as0[4], ad0[4], as1[4], ad1[4];
    #pragma unroll
    for (int j = 0; j < 4; j++) {
        as0[j] = __ldg(att_src + tc + j);
        ad0[j] = __ldg(att_dst + tc + j);
        as1[j] = __ldg(att_src + tc + 64 + j);
        ad1[j] = __ldg(att_dst + tc + 64 + j);
    }
    int h0 = tc >> 5;                       // 0 or 1; group1 head = h0+2
    #pragma unroll
    for (int i = 0; i < 4; i++) {
        float ps0 = 0.f, pd0 = 0.f, ps1 = 0.f, pd1 = 0.f;
        #pragma unroll
        for (int j = 0; j < 4; j++) {
            ps0 += acc0[i][j] * as0[j];
            pd0 += acc0[i][j] * ad0[j];
            ps1 += acc1[i][j] * as1[j];
            pd1 += acc1[i][j] * ad1[j];
        }
        #pragma unroll
        for (int o = 1; o < 8; o <<= 1) {
            ps0 += __shfl_xor_sync(0xffffffffu, ps0, o);
            pd0 += __shfl_xor_sync(0xffffffffu, pd0, o);
            ps1 += __shfl_xor_sync(0xffffffffu, ps1, o);
            pd1 += __shfl_xor_sync(0xffffffffu, pd1, o);
        }
        int row = row0 + tr + i;
        if ((t & 7) == 0 && row < N_NODES) {
            g_asrc[row * 4 + h0]     = ps0;
            g_asrc[row * 4 + h0 + 2] = ps1;
            g_adst[row * 4 + h0]     = pd0;
            g_adst[row * 4 + h0 + 2] = pd1;
        }
    }
}

// ---------------- edge pass: atomic scatter, deferred normalization --------
// Each warp handles exactly 32 edges (800000/32 = 25000 warps, no tail).
// Per edge: broadcast asrc/adst, per-lane fp16 gather of 4 channels,
// red.global.add.v4.f32 into out[dst]; lane 0 adds 4 head exps to den.
__global__ __launch_bounds__(256) void edge_kernel(const int* __restrict__ ei) {
    const int lane = threadIdx.x & 31;
    const int gw = (int)((blockIdx.x * 256 + threadIdx.x) >> 5);
    const int head = lane >> 3;
    const int is64 = g_is64;

    int e = gw * 32 + lane;
    int s_r, d_r;
    if (is64) { s_r = ei[2 * e]; d_r = ei[2 * (N_EDGES + e)]; }
    else      { s_r = ei[e];     d_r = ei[N_EDGES + e]; }

    #pragma unroll 4
    for (int i = 0; i < 32; i++) {
        int s = __shfl_sync(0xffffffffu, s_r, i);
        int d = __shfl_sync(0xffffffffu, d_r, i);

        float4 as = __ldg(reinterpret_cast<const float4*>(g_asrc + s * 4));
        float4 ad = __ldg(reinterpret_cast<const float4*>(g_adst + d * 4));
        float e0 = as.x + ad.x, e1 = as.y + ad.y;
        float e2 = as.z + ad.z, e3 = as.w + ad.w;
        e0 = e0 > 0.f ? e0 : NEG_SLOPE * e0;
        e1 = e1 > 0.f ? e1 : NEG_SLOPE * e1;
        e2 = e2 > 0.f ? e2 : NEG_SLOPE * e2;
        e3 = e3 > 0.f ? e3 : NEG_SLOPE * e3;
        float eh  = head == 0 ? e0 : (head == 1 ? e1 : (head == 2 ? e2 : e3));
        float exh = __expf(eh);

        H2x2 v;
        v.u = __ldg(reinterpret_cast<const uint2*>(
            g_hh + (size_t)s * 128 + lane * 4));
        float2 f0 = __half22float2(v.h[0]);
        float2 f1 = __half22float2(v.h[1]);

        float* outp = g_out + (size_t)d * 128 + lane * 4;
        asm volatile("red.global.add.v4.f32 [%0], {%1,%2,%3,%4};"
                     :: "l"(outp), "f"(f0.x * exh), "f"(f0.y * exh),
                        "f"(f1.x * exh), "f"(f1.y * exh)
                     : "memory");

        // denom: head exps live in lanes 0, 8, 16, 24
        float x1 = __shfl_sync(0xffffffffu, exh, 8);
        float x2 = __shfl_sync(0xffffffffu, exh, 16);
        float x3 = __shfl_sync(0xffffffffu, exh, 24);
        if (lane == 0) {
            asm volatile("red.global.add.v4.f32 [%0], {%1,%2,%3,%4};"
                         :: "l"(g_den + (size_t)d * 4), "f"(exh), "f"(x1),
                            "f"(x2), "f"(x3)
                         : "memory");
        }
    }
}

// ---------------- node epilogue: self-loop + normalize + LN + GELU ---------
__global__ __launch_bounds__(256) void node_kernel(const float* __restrict__ x,
                                                   const float* __restrict__ bias,
                                                   const float* __restrict__ gamma,
                                                   const float* __restrict__ beta,
                                                   float* __restrict__ out) {
    int n = (int)(((size_t)blockIdx.x * blockDim.x + threadIdx.x) >> 5);
    int lane = threadIdx.x & 31;
    if (n >= N_NODES) return;
    int head = lane >> 3;

    // self-loop attention exp per head
    float4 as = *reinterpret_cast<const float4*>(g_asrc + (size_t)n * 4);
    float4 ad = *reinterpret_cast<const float4*>(g_adst + (size_t)n * 4);
    float e0 = as.x + ad.x, e1 = as.y + ad.y;
    float e2 = as.z + ad.z, e3 = as.w + ad.w;
    e0 = e0 > 0.f ? e0 : NEG_SLOPE * e0;
    e1 = e1 > 0.f ? e1 : NEG_SLOPE * e1;
    e2 = e2 > 0.f ? e2 : NEG_SLOPE * e2;
    e3 = e3 > 0.f ? e3 : NEG_SLOPE * e3;
    float ex0 = __expf(e0), ex1 = __expf(e1), ex2 = __expf(e2), ex3 = __expf(e3);

    float4 dn = *reinterpret_cast<const float4*>(g_den + (size_t)n * 4);
    float den = head == 0 ? dn.x + ex0 : (head == 1 ? dn.y + ex1
              : (head == 2 ? dn.z + ex2 : dn.w + ex3));
    float exh = head == 0 ? ex0 : (head == 1 ? ex1 : (head == 2 ? ex2 : ex3));
    float inv = 1.f / den;

    float4 acc = *reinterpret_cast<const float4*>(g_out + (size_t)n * 128 + lane * 4);
    H2x2 v;
    v.u = *reinterpret_cast<const uint2*>(g_hh + (size_t)n * 128 + lane * 4);
    float2 f0 = __half22float2(v.h[0]);
    float2 f1 = __half22float2(v.h[1]);
    float4 b4 = __ldg(reinterpret_cast<const float4*>(bias + lane * 4));

    float v0 = (acc.x + f0.x * exh) * inv + b4.x;
    float v1 = (acc.y + f0.y * exh) * inv + b4.y;
    float v2 = (acc.z + f1.x * exh) * inv + b4.z;
    float v3 = (acc.w + f1.y * exh) * inv + b4.w;

    // LayerNorm over 128 channels (warp allreduce; 4 values/lane)
    float s = v0 + v1 + v2 + v3;
    #pragma unroll
    for (int o = 16; o > 0; o >>= 1) s += __shfl_xor_sync(0xffffffffu, s, o);
    float mu = s * (1.f / 128.f);
    float d0 = v0 - mu, d1 = v1 - mu, d2 = v2 - mu, d3 = v3 - mu;
    float q = d0 * d0 + d1 * d1 + d2 * d2 + d3 * d3;
    #pragma unroll
    for (int o = 16; o > 0; o >>= 1) q += __shfl_xor_sync(0xffffffffu, q, o);
    float rstd = rsqrtf(q * (1.f / 128.f) + LN_EPS);

    float4 gm = __ldg(reinterpret_cast<const float4*>(gamma + lane * 4));
    float4 bt = __ldg(reinterpret_cast<const float4*>(beta + lane * 4));
    float4 xv = *reinterpret_cast<const float4*>(x + (size_t)n * 128 + lane * 4);

    float h0 = d0 * rstd * gm.x + bt.x + xv.x;
    float h1 = d1 * rstd * gm.y + bt.y + xv.y;
    float h2 = d2 * rstd * gm.z + bt.z + xv.z;
    float h3 = d3 * rstd * gm.w + bt.w + xv.w;

    const float k = 0.70710678118654752f;
    float4 r;
    r.x = 0.5f * h0 * (1.f + erff(h0 * k));
    r.y = 0.5f * h1 * (1.f + erff(h1 * k));
    r.z = 0.5f * h2 * (1.f + erff(h2 * k));
    r.w = 0.5f * h3 * (1.f + erff(h3 * k));
    *reinterpret_cast<float4*>(out + (size_t)n * 128 + lane * 4) = r;
}

// ---------------- launch ----------------------------------------------------
extern "C" void kernel_launch(void* const* d_in, const int* in_sizes, int n_in,
                              void* d_out, int out_size) {
    const float* x       = (const float*)d_in[0];
    const int*   ei      = (const int*)d_in[1];   // int32 or int64 (detected)
    const float* W       = (const float*)d_in[2];
    const float* att_src = (const float*)d_in[3];
    const float* att_dst = (const float*)d_in[4];
    const float* bias    = (const float*)d_in[5];
    const float* gamma   = (const float*)d_in[6];
    const float* beta    = (const float*)d_in[7];
    float* out = (float*)d_out;

    cudaFuncSetAttribute(gemm_kernel, cudaFuncAttributeMaxDynamicSharedMemorySize,
                         65536);

    detect_kernel<<<1, 512>>>(ei);
    zero_kernel<<<512, 256>>>();
    gemm_kernel<<<(N_NODES + 63) / 64, 256, 65536>>>(x, W, att_src, att_dst);
    edge_kernel<<<3125, 256>>>(ei);
    node_kernel<<<(N_NODES + 7) / 8, 256>>>(x, bias, gamma, beta, out);
}